// round 4
// baseline (speedup 1.0000x reference)
#include <cuda_runtime.h>

#define N_NODES 50000
#define N_EDGES 800000
#define CH 128

// ---------------- scratch (static device globals; no runtime alloc) ----------------
__device__ float g_featA[N_NODES * CH];   // layer-1 output
__device__ float g_featB[N_NODES * CH];   // layer-2 output
__device__ float g_agg[N_NODES * CH];     // per-layer aggregation buffer
__device__ int   g_deg[N_NODES];
__device__ int   g_start[N_NODES];
__device__ int   g_cursor[N_NODES];
__device__ int   g_src[N_EDGES];          // src ids grouped by dst (CSR)
__device__ int   g_is64;                  // 1 if edge_index buffer is int64-laid-out

// ---------------- edge-index layout detection ----------------
// int64 layout: every odd int32 word (hi half) of the first 4096 edges is 0
// (node ids < 50000 always fit in the low word, values are non-negative).
// int32 layout: odd words are random ids; P(all 4096 == 0) ~ (1/50000)^4096 ~ 0.
__global__ void detect_kernel(const int* __restrict__ ei32) {
    __shared__ int any_nz;
    if (threadIdx.x == 0) any_nz = 0;
    __syncthreads();
    for (int i = threadIdx.x; i < 4096; i += blockDim.x)
        if (ei32[2 * i + 1] != 0) any_nz = 1;   // benign race (only sets 1)
    __syncthreads();
    if (threadIdx.x == 0) g_is64 = any_nz ? 0 : 1;
}

__device__ __forceinline__ int load_idx(const int* ei32, long long pos) {
    // pos = logical element index into the [2, N_EDGES] id array
    int v = g_is64 ? ei32[2 * pos] : ei32[pos];
    if (v < 0 || v >= N_NODES) v = 0;           // crash-proof clamp
    return v;
}

// ---------------- CSR build ----------------
__global__ void zero_deg_kernel() {
    int i = blockIdx.x * blockDim.x + threadIdx.x;
    if (i < N_NODES) g_deg[i] = 0;
}

__global__ void hist_kernel(const int* __restrict__ ei32) {
    int e = blockIdx.x * blockDim.x + threadIdx.x;
    if (e < N_EDGES) {
        int d = load_idx(ei32, (long long)N_EDGES + e);
        atomicAdd(&g_deg[d], 1);
    }
}

// Single-block exclusive scan over g_deg -> g_start, g_cursor (1024 threads).
__global__ void scan_kernel() {
    __shared__ int warp_sums[32];
    __shared__ int carry_s;
    int tid = threadIdx.x, lane = tid & 31, wid = tid >> 5;
    if (tid == 0) carry_s = 0;
    __syncthreads();
    for (int base = 0; base < N_NODES; base += 1024) {
        int i = base + tid;
        int v = (i < N_NODES) ? g_deg[i] : 0;
        int val = v;
        #pragma unroll
        for (int off = 1; off < 32; off <<= 1) {
            int t = __shfl_up_sync(0xffffffffu, val, off);
            if (lane >= off) val += t;
        }
        if (lane == 31) warp_sums[wid] = val;
        __syncthreads();
        if (wid == 0) {
            int s = warp_sums[lane];
            int sv = s;
            #pragma unroll
            for (int off = 1; off < 32; off <<= 1) {
                int t = __shfl_up_sync(0xffffffffu, sv, off);
                if (lane >= off) sv += t;
            }
            warp_sums[lane] = sv - s;   // exclusive warp offsets
        }
        __syncthreads();
        int incl = val + warp_sums[wid];
        int carry = carry_s;
        __syncthreads();                 // everyone reads carry before it is updated
        if (i < N_NODES) {
            int excl = carry + incl - v;
            g_start[i]  = excl;
            g_cursor[i] = excl;
        }
        if (tid == 1023) carry_s = carry + incl;
        __syncthreads();
    }
}

__global__ void fill_kernel(const int* __restrict__ ei32) {
    int e = blockIdx.x * blockDim.x + threadIdx.x;
    if (e < N_EDGES) {
        int d = load_idx(ei32, (long long)N_EDGES + e);
        int s = load_idx(ei32, e);
        int p = atomicAdd(&g_cursor[d], 1);
        if (p >= 0 && p < N_EDGES) g_src[p] = s;
    }
}

// ---------------- mean aggregation: one warp per dst node ----------------
// sel: 0 = external x, 1 = g_featA, 2 = g_featB. Output -> g_agg.
__global__ void agg_kernel(const float* __restrict__ xext, int sel, int nrows) {
    int gw = (int)((blockIdx.x * blockDim.x + threadIdx.x) >> 5);
    int lane = threadIdx.x & 31;
    if (gw >= nrows) return;
    const float* feat = (sel == 0) ? xext : ((sel == 1) ? g_featA : g_featB);
    const float4* base = (const float4*)feat;
    int s = g_start[gw];
    int n = g_deg[gw];
    float4 acc = make_float4(0.f, 0.f, 0.f, 0.f);
    for (int e = 0; e < n; e++) {
        int src = g_src[s + e];
        float4 v = base[src * 32 + lane];          // x fits in L2 -> L2-rate gather
        acc.x += v.x; acc.y += v.y; acc.z += v.z; acc.w += v.w;
    }
    float inv = (n > 0) ? 1.0f / (float)n : 0.0f;  // deg==0 -> agg row = 0
    ((float4*)g_agg)[gw * 32 + lane] =
        make_float4(acc.x * inv, acc.y * inv, acc.z * inv, acc.w * inv);
}

// ---------------- fused GEMM + bias + PReLU ----------------
// out = PReLU( g_agg @ Wl^T + bl + X @ Wr^T ), per-channel slope pa.
// Tile: BM=64, BN=128 (all cols), BK=16, 256 threads, 8x4 register tile.
__global__ __launch_bounds__(256, 4) void gemm_kernel(
    const float* __restrict__ xext, int xsel,
    const float* __restrict__ Wl, const float* __restrict__ bl,
    const float* __restrict__ Wr, const float* __restrict__ pa,
    float* __restrict__ oext, int osel, int M)
{
    const float* X = (xsel == 0) ? xext : ((xsel == 1) ? g_featA : g_featB);
    float*       O = (osel == 0) ? oext : ((osel == 1) ? g_featA : g_featB);

    __shared__ float As[16][65];    // [k][m], padded: broadcast reads
    __shared__ float Bs[16][132];   // [k][n], padded +4 keeps 16B alignment

    int tid = threadIdx.x;
    int block_row = blockIdx.x * 64;
    int tn = tid & 31;    // column group: cols tn*4 .. tn*4+3
    int tm = tid >> 5;    // warp id = row group: rows tm*8 .. tm*8+7

    float acc[8][4];
    #pragma unroll
    for (int i = 0; i < 8; i++)
        #pragma unroll
        for (int j = 0; j < 4; j++) acc[i][j] = 0.f;

    #pragma unroll 1
    for (int chunk = 0; chunk < 16; chunk++) {
        const float* Aptr; const float* Wptr; int kbase;
        if (chunk < 8) { Aptr = g_agg; Wptr = Wl; kbase = chunk * 16; }
        else           { Aptr = X;     Wptr = Wr; kbase = (chunk - 8) * 16; }

        // A tile: rows block_row..+63, k kbase..+15 (transposed into As)
        {
            int r  = tid >> 2;            // 0..63
            int kq = tid & 3;             // 0..3
            int grow = block_row + r;
            float4 v = make_float4(0.f, 0.f, 0.f, 0.f);
            if (grow < M)
                v = *(const float4*)(Aptr + (size_t)grow * CH + kbase + kq * 4);
            As[kq * 4 + 0][r] = v.x;
            As[kq * 4 + 1][r] = v.y;
            As[kq * 4 + 2][r] = v.z;
            As[kq * 4 + 3][r] = v.w;
        }
        // W tile: Bs[k][n] = W[n][kbase+k]
        {
            #pragma unroll
            for (int l = 0; l < 2; l++) {
                int s  = tid + l * 256;   // 0..511
                int n  = s >> 2;          // 0..127
                int kq = s & 3;
                float4 v = *(const float4*)(Wptr + n * CH + kbase + kq * 4);
                Bs[kq * 4 + 0][n] = v.x;
                Bs[kq * 4 + 1][n] = v.y;
                Bs[kq * 4 + 2][n] = v.z;
                Bs[kq * 4 + 3][n] = v.w;
            }
        }
        __syncthreads();

        #pragma unroll
        for (int k = 0; k < 16; k++) {
            float4 b4 = *(const float4*)&Bs[k][tn * 4];  // conflict-free LDS.128
            float a[8];
            #pragma unroll
            for (int i = 0; i < 8; i++) a[i] = As[k][tm * 8 + i];  // warp broadcast
            #pragma unroll
            for (int i = 0; i < 8; i++) {
                acc[i][0] += a[i] * b4.x;
                acc[i][1] += a[i] * b4.y;
                acc[i][2] += a[i] * b4.z;
                acc[i][3] += a[i] * b4.w;
            }
        }
        __syncthreads();
    }

    // epilogue: bias + PReLU, float4 stores
    int col = tn * 4;
    float4 bb = *(const float4*)(bl + col);
    float4 aa = *(const float4*)(pa + col);
    #pragma unroll
    for (int i = 0; i < 8; i++) {
        int grow = block_row + tm * 8 + i;
        if (grow < M) {
            float v0 = acc[i][0] + bb.x;
            float v1 = acc[i][1] + bb.y;
            float v2 = acc[i][2] + bb.z;
            float v3 = acc[i][3] + bb.w;
            float4 o;
            o.x = (v0 > 0.f) ? v0 : aa.x * v0;
            o.y = (v1 > 0.f) ? v1 : aa.y * v1;
            o.z = (v2 > 0.f) ? v2 : aa.z * v2;
            o.w = (v3 > 0.f) ? v3 : aa.w * v3;
            *(float4*)(O + (size_t)grow * CH + col) = o;
        }
    }
}

// ---------------- launch ----------------
extern "C" void kernel_launch(void* const* d_in, const int* in_sizes, int n_in,
                              void* d_out, int out_size) {
    const float* x    = (const float*)d_in[0];
    const int*   ei32 = (const int*)d_in[1];     // layout auto-detected on device
    int wb = n_in - 12;                          // weights are the LAST 12 inputs
    const float* Wl0 = (const float*)d_in[wb + 0];
    const float* bl0 = (const float*)d_in[wb + 1];
    const float* Wr0 = (const float*)d_in[wb + 2];
    const float* a0  = (const float*)d_in[wb + 3];
    const float* Wl1 = (const float*)d_in[wb + 4];
    const float* bl1 = (const float*)d_in[wb + 5];
    const float* Wr1 = (const float*)d_in[wb + 6];
    const float* a1  = (const float*)d_in[wb + 7];
    const float* Wl2 = (const float*)d_in[wb + 8];
    const float* bl2 = (const float*)d_in[wb + 9];
    const float* Wr2 = (const float*)d_in[wb + 10];
    const float* a2  = (const float*)d_in[wb + 11];
    float* out = (float*)d_out;

    const int EB = (N_EDGES + 255) / 256;       // 3125
    const int NB = (N_NODES + 255) / 256;       // 196
    const int GM = (N_NODES + 63) / 64;         // 782

    // CSR build (per call; deterministic work)
    detect_kernel<<<1, 256>>>(ei32);
    zero_deg_kernel<<<NB, 256>>>();
    hist_kernel<<<EB, 256>>>(ei32);
    scan_kernel<<<1, 1024>>>();
    fill_kernel<<<EB, 256>>>(ei32);

    // Layer 1: agg(x) -> g_agg; out -> g_featA
    agg_kernel<<<(N_NODES + 7) / 8, 256>>>(x, 0, N_NODES);
    gemm_kernel<<<GM, 256>>>(x, 0, Wl0, bl0, Wr0, a0, nullptr, 1, N_NODES);

    // Layer 2: agg(featA) -> g_agg; out -> g_featB
    agg_kernel<<<(N_NODES + 7) / 8, 256>>>(nullptr, 1, N_NODES);
    gemm_kernel<<<GM, 256>>>(nullptr, 1, Wl1, bl1, Wr1, a1, nullptr, 2, N_NODES);

    // Layer 3: only rows < 1024 are needed
    agg_kernel<<<1024 / 8, 256>>>(nullptr, 2, 1024);
    gemm_kernel<<<1024 / 64, 256>>>(nullptr, 2, Wl2, bl2, Wr2, a2, out, 0, 1024);
}